// round 12
// baseline (speedup 1.0000x reference)
#include <cuda_runtime.h>
#include <cuda_fp16.h>
#include <cstdint>

// ---------------------------------------------------------------------------
// CrossAttention on GB300 (sm_103a; plain compute_103 -> mma.sync fp16).
// R12: single fp16 x single fp16 in ALL GEMMs (error budget measured-safe),
// conv on a 3-stage cp.async pipeline with one barrier per chunk.
// ---------------------------------------------------------------------------

#define NB   4
#define CCH  512
#define HW   1024
#define NHD  8
#define DHEAD 128

typedef __half fp16;

// Scratch (no allocations -> __device__ globals)
__device__ fp16  g_w1[6][9 * 512 * 512];           // [conv][r][co][ci]
__device__ fp16  g_x1[2][NB * HW * CCH];           // [n][hw][ci]
__device__ fp16  g_q1[6][NB * CCH * HW];           // kl,ql,vl,kg,qg,vg
__device__ float g_att[2][NB * NHD * 512 * 512];   // pre-softmax
__device__ fp16  g_a1[2][NB * NHD * 512 * 512];    // post-softmax fp16
__device__ fp16  g_y1[2][NB * CCH * HW];           // y_g, y_l
__device__ fp16  g_wp1[2][512 * 512];

// ============================ helpers =======================================
__device__ __forceinline__ uint32_t smem_u32(const void* p) {
    uint32_t a;
    asm("{ .reg .u64 t; cvta.to.shared.u64 t, %1; cvt.u32.u64 %0, t; }"
        : "=r"(a) : "l"(p));
    return a;
}

__device__ __forceinline__ void mma_f16(float* c, const uint32_t* a, const uint32_t* b) {
    asm volatile(
        "mma.sync.aligned.m16n8k16.row.col.f32.f16.f16.f32 "
        "{%0,%1,%2,%3}, {%4,%5,%6,%7}, {%8,%9}, {%0,%1,%2,%3};"
        : "+f"(c[0]), "+f"(c[1]), "+f"(c[2]), "+f"(c[3])
        : "r"(a[0]), "r"(a[1]), "r"(a[2]), "r"(a[3]), "r"(b[0]), "r"(b[1]));
}

#define LDSM4(r0, r1, r2, r3, addr) \
    asm volatile("ldmatrix.sync.aligned.m8n8.x4.shared.b16 {%0,%1,%2,%3}, [%4];" \
                 : "=r"(r0), "=r"(r1), "=r"(r2), "=r"(r3) : "r"(addr))

#define LDSM2T(r0, r1, addr) \
    asm volatile("ldmatrix.sync.aligned.m8n8.x2.trans.shared.b16 {%0,%1}, [%2];" \
                 : "=r"(r0), "=r"(r1) : "r"(addr))

#define CPA(dst, src, sz) \
    asm volatile("cp.async.ca.shared.global [%0], [%1], 16, %2;" \
                 :: "r"(dst), "l"(src), "r"(sz) : "memory")
#define CP_COMMIT() asm volatile("cp.async.commit_group;" ::: "memory")
#define CP_WAIT1()  asm volatile("cp.async.wait_group 1;" ::: "memory")
#define CP_WAIT0()  asm volatile("cp.async.wait_group 0;" ::: "memory")

// ============================ prep kernels ==================================
// w [co][ci][3][3] -> [conv][r][co][ci] fp16
__global__ void prep_w3(const float* __restrict__ w0, const float* __restrict__ w1,
                        const float* __restrict__ w2, const float* __restrict__ w3,
                        const float* __restrict__ w4, const float* __restrict__ w5,
                        fp16* __restrict__ wo) {
    const float* ws[6] = {w0, w1, w2, w3, w4, w5};
    int conv = blockIdx.y;
    const float* w = ws[conv];
    int t = blockIdx.x * 256 + threadIdx.x;
    int co = t >> 9, ci = t & 511;
    float v[9];
#pragma unroll
    for (int r = 0; r < 9; ++r) v[r] = w[(size_t)t * 9 + r];
#pragma unroll
    for (int r = 0; r < 9; ++r)
        wo[(((size_t)conv * 9 + r) * 512 + co) * 512 + ci] = __float2half_rn(v[r]);
}
__global__ void prep_wp(const float* __restrict__ wp1, const float* __restrict__ wp2,
                        fp16* __restrict__ wo) {
    int pidx = blockIdx.y;
    const float* w = pidx ? wp2 : wp1;
    int idx = blockIdx.x * 256 + threadIdx.x;
    wo[(size_t)pidx * 512 * 512 + idx] = __float2half_rn(w[idx]);
}
// x [n][c][hw] -> xt [n][hw][c] fp16
__global__ void transpose_x(const float* __restrict__ xl, const float* __restrict__ xg,
                            fp16* __restrict__ xt1) {
    __shared__ float tile[32][33];
    int zt = blockIdx.z, tsel = zt >> 2, n = zt & 3;
    const float* x = (tsel ? xg : xl) + (size_t)n * (CCH * HW);
    size_t ob = (size_t)tsel * NB * HW * CCH + (size_t)n * (HW * CCH);
    int hw0 = blockIdx.x * 32, c0 = blockIdx.y * 32;
    int tx = threadIdx.x, ty = threadIdx.y;
#pragma unroll
    for (int i = 0; i < 32; i += 8)
        tile[ty + i][tx] = x[(size_t)(c0 + ty + i) * HW + hw0 + tx];
    __syncthreads();
#pragma unroll
    for (int i = 0; i < 32; i += 8)
        xt1[ob + (size_t)(hw0 + ty + i) * CCH + c0 + tx] =
            __float2half_rn(tile[tx][ty + i]);
}

// ============================ layout consts =================================
#define ROWB 80
#define MATB (128 * ROWB)             // 10240
#define ROW2 272
#define MATB2 (32 * ROW2)             // 8704
#define STG2 (2 * MATB)               // nn stage: A B          20480
#define SM23 (3 * STG2)               // conv 3-stage           61440
#define SM22 (2 * STG2)               // qk 2-stage             40960
#define STGN (MATB + MATB2)           // nt stage: A B          18944
#define SMN  (2 * STGN)               // 37888

// ======================= mma inner phases (single A) ========================
__device__ __forceinline__ void mma_phase_nn(uint32_t st, uint32_t a_base,
                                             uint32_t b_base, float acc[4][4][4]) {
    uint32_t sA = st, sB = st + MATB;
#pragma unroll
    for (int kt = 0; kt < 2; ++kt) {
        uint32_t aa[4][4], bb[4][2];
#pragma unroll
        for (int mt = 0; mt < 4; ++mt) {
            uint32_t ad = a_base + (uint32_t)(mt * 16 * ROWB + kt * 32);
            LDSM4(aa[mt][0], aa[mt][1], aa[mt][2], aa[mt][3], sA + ad);
        }
#pragma unroll
        for (int p = 0; p < 2; ++p) {
            uint32_t bd = b_base + (uint32_t)(p * 16 * ROWB + kt * 32);
            uint32_t r0, r1, r2, r3;
            LDSM4(r0, r1, r2, r3, sB + bd);
            bb[2 * p][0] = r0; bb[2 * p][1] = r2;
            bb[2 * p + 1][0] = r1; bb[2 * p + 1][1] = r3;
        }
#pragma unroll
        for (int mt = 0; mt < 4; ++mt)
#pragma unroll
            for (int nt = 0; nt < 4; ++nt)
                mma_f16(acc[mt][nt], aa[mt], bb[nt]);
    }
}

__device__ __forceinline__ void mma_phase_nt(uint32_t st, uint32_t a_base,
                                             uint32_t bt_base, float acc[4][4][4]) {
    uint32_t sA = st, sB = st + MATB;
#pragma unroll
    for (int kt = 0; kt < 2; ++kt) {
        uint32_t aa[4][4], bb[4][2];
#pragma unroll
        for (int mt = 0; mt < 4; ++mt) {
            uint32_t ad = a_base + (uint32_t)(mt * 16 * ROWB + kt * 32);
            LDSM4(aa[mt][0], aa[mt][1], aa[mt][2], aa[mt][3], sA + ad);
        }
#pragma unroll
        for (int nt = 0; nt < 4; ++nt) {
            uint32_t bd = bt_base + (uint32_t)(kt * 16 * ROW2 + nt * 16);
            LDSM2T(bb[nt][0], bb[nt][1], sB + bd);
        }
#pragma unroll
        for (int mt = 0; mt < 4; ++mt)
#pragma unroll
            for (int nt = 0; nt < 4; ++nt)
                mma_f16(acc[mt][nt], aa[mt], bb[nt]);
    }
}

// ========== conv 3x3: single fp16, 3-stage cp.async, 1 sync/chunk ===========
// grid (8 s-tiles, 4 co-tiles, 24 conv*n)
__global__ __launch_bounds__(256, 2)
void conv_mma_kernel(const fp16* __restrict__ xt1, const fp16* __restrict__ w1,
                     fp16* __restrict__ q1) {
    extern __shared__ unsigned char dsm[];
    const uint32_t sb = smem_u32(dsm);

    int tid = threadIdx.x, wid = tid >> 5, lid = tid & 31;
    int warp_m = wid >> 2, warp_n = wid & 3;
    int sp0 = blockIdx.x * 128, co0 = blockIdx.y * 128;
    int conv = blockIdx.z >> 2, n = blockIdx.z & 3;
    const fp16* xb = xt1 + ((size_t)(conv < 3 ? 0 : 1) * NB + n) * (HW * CCH);
    const fp16* wb = w1 + (size_t)conv * (9 * 512 * 512);
    fp16* o1 = q1 + ((size_t)conv * NB + n) * (CCH * HW);

    float acc[4][4][4];
#pragma unroll
    for (int mt = 0; mt < 4; ++mt)
#pragma unroll
        for (int nt = 0; nt < 4; ++nt)
#pragma unroll
            for (int k = 0; k < 4; ++k) acc[mt][nt][k] = 0.f;

    int grp = lid >> 3, lr = lid & 7;
    uint32_t a_base = (uint32_t)((warp_m * 64 + (grp & 1) * 8 + lr) * ROWB + (grp >> 1) * 16);
    uint32_t b_base = (uint32_t)((warp_n * 32 + (grp & 1) * 8 + lr) * ROWB + (grp >> 1) * 16);

    int row = tid >> 1, half = tid & 1;
    uint32_t dstA = (uint32_t)(row * ROWB + half * 32);

    auto prefetch = [&](int ch, int st) {
        uint32_t s0b = sb + st * STG2;
        int r = ch >> 4, ci0 = (ch & 15) << 5;
        int dy = r / 3 - 1, dx = r % 3 - 1;
        size_t wof = ((size_t)r * 512 + co0 + row) * 512 + ci0 + half * 16;
        uint32_t da = s0b + dstA;
        CPA(da,      wb + wof,     16u);
        CPA(da + 16, wb + wof + 8, 16u);
        int s = sp0 + row;
        int yy = (s >> 5) + dy, xx = (s & 31) + dx;
        bool ok = ((unsigned)yy < 32u) && ((unsigned)xx < 32u);
        size_t xof = ok ? ((size_t)(yy * 32 + xx) * 512 + ci0 + half * 16) : 0;
        uint32_t sz = ok ? 16u : 0u;
        uint32_t db = s0b + MATB + dstA;
        CPA(db,      xb + xof,     sz);
        CPA(db + 16, xb + xof + 8, sz);
    };

    // 3-stage pipeline, one barrier per chunk
    prefetch(0, 0); CP_COMMIT();
    prefetch(1, 1); CP_COMMIT();
    for (int ch = 0; ch < 144; ++ch) {
        if (ch < 142) CP_WAIT1(); else CP_WAIT0();
        __syncthreads();
        mma_phase_nn(sb + (ch % 3) * STG2, a_base, b_base, acc);
        if (ch + 2 < 144) { prefetch(ch + 2, (ch + 2) % 3); CP_COMMIT(); }
    }

#pragma unroll
    for (int mt = 0; mt < 4; ++mt) {
        int m = co0 + warp_m * 64 + mt * 16 + (lid >> 2);
#pragma unroll
        for (int nt = 0; nt < 4; ++nt) {
            int sc = sp0 + warp_n * 32 + nt * 8 + (lid & 3) * 2;
            __half2 p0 = __floats2half2_rn(acc[mt][nt][0], acc[mt][nt][1]);
            __half2 p1 = __floats2half2_rn(acc[mt][nt][2], acc[mt][nt][3]);
            *(uint32_t*)&o1[(size_t)m * HW + sc] = *(uint32_t*)&p0;
            *(uint32_t*)&o1[(size_t)(m + 8) * HW + sc] = *(uint32_t*)&p1;
        }
    }
}

// ================== QK^T: single fp16, 2-stage cp.async =====================
// grid (4 ck, 4 cq, 64): z<32 -> (q_g,k_l)->att0 ; z>=32 -> (q_l,k_g)->att1
__global__ __launch_bounds__(256, 2)
void qk_mma_kernel(const fp16* __restrict__ qk1, float* __restrict__ att) {
    extern __shared__ unsigned char dsm[];
    const uint32_t sb = smem_u32(dsm);
    const size_t QKV_N = (size_t)NB * CCH * HW;
    const size_t ATT_N = (size_t)NB * NHD * 512 * 512;

    int tid = threadIdx.x, wid = tid >> 5, lid = tid & 31;
    int warp_m = wid >> 2, warp_n = wid & 3;
    int z = blockIdx.z, sel = z >> 5, nh = z & 31;
    int n = nh >> 3, h = nh & 7;
    int ck0 = blockIdx.x * 128, cq0 = blockIdx.y * 128;
    size_t base = (size_t)n * (CCH * HW) + h * DHEAD;
    const fp16* qb = qk1 + (sel ? 1 : 4) * QKV_N + base;
    const fp16* kb = qk1 + (sel ? 3 : 0) * QKV_N + base;

    float acc[4][4][4];
#pragma unroll
    for (int mt = 0; mt < 4; ++mt)
#pragma unroll
        for (int nt = 0; nt < 4; ++nt)
#pragma unroll
            for (int kk = 0; kk < 4; ++kk) acc[mt][nt][kk] = 0.f;

    int grp = lid >> 3, lr = lid & 7;
    uint32_t a_base = (uint32_t)((warp_m * 64 + (grp & 1) * 8 + lr) * ROWB + (grp >> 1) * 16);
    uint32_t b_base = (uint32_t)((warp_n * 32 + (grp & 1) * 8 + lr) * ROWB + (grp >> 1) * 16);

    int row = tid >> 1, half = tid & 1;
    uint32_t dstA = (uint32_t)(row * ROWB + half * 32);

    auto prefetch = [&](int ch, int st) {
        uint32_t s0b = sb + st * STG2;
        int ci0 = ch << 5;
        size_t qof = (size_t)(cq0 + row) * HW + ci0 + half * 16;
        size_t kof = (size_t)(ck0 + row) * HW + ci0 + half * 16;
        uint32_t da = s0b + dstA;
        CPA(da,      qb + qof,     16u);
        CPA(da + 16, qb + qof + 8, 16u);
        uint32_t db = s0b + MATB + dstA;
        CPA(db,      kb + kof,     16u);
        CPA(db + 16, kb + kof + 8, 16u);
    };

    prefetch(0, 0); CP_COMMIT();
    for (int ch = 0; ch < 4; ++ch) {
        if (ch + 1 < 4) { prefetch(ch + 1, (ch + 1) & 1); CP_COMMIT(); CP_WAIT1(); }
        else CP_WAIT0();
        __syncthreads();
        mma_phase_nn(sb + (ch & 1) * STG2, a_base, b_base, acc);
        __syncthreads();
    }

    const float SC = 0.08838834764831845f;   // 1/sqrt(128)
    float* ab = att + sel * ATT_N + (size_t)(n * NHD + h) * 512 * 512;
#pragma unroll
    for (int mt = 0; mt < 4; ++mt) {
        int m = cq0 + warp_m * 64 + mt * 16 + (lid >> 2);
#pragma unroll
        for (int nt = 0; nt < 4; ++nt) {
            int sc = ck0 + warp_n * 32 + nt * 8 + (lid & 3) * 2;
            *(float2*)(ab + (size_t)m * 512 + sc) =
                make_float2(acc[mt][nt][0] * SC, acc[mt][nt][1] * SC);
            *(float2*)(ab + (size_t)(m + 8) * 512 + sc) =
                make_float2(acc[mt][nt][2] * SC, acc[mt][nt][3] * SC);
        }
    }
}

// ----------------- softmax: fp32 in -> fp16 out ------------------------------
__global__ void softmax_kernel(const float* __restrict__ att, fp16* __restrict__ a1) {
    int row  = blockIdx.x * 8 + (threadIdx.x >> 5);
    int lane = threadIdx.x & 31;
    const float* p = att + (size_t)row * 512;
    fp16* po = a1 + (size_t)row * 512;
    float v[16];
    float m = -1e30f;
#pragma unroll
    for (int i = 0; i < 16; ++i) { v[i] = p[lane + i * 32]; m = fmaxf(m, v[i]); }
#pragma unroll
    for (int o = 16; o; o >>= 1) m = fmaxf(m, __shfl_xor_sync(0xffffffffu, m, o));
    float s = 0.f;
#pragma unroll
    for (int i = 0; i < 16; ++i) { v[i] = __expf(v[i] - m); s += v[i]; }
#pragma unroll
    for (int o = 16; o; o >>= 1) s += __shfl_xor_sync(0xffffffffu, s, o);
    float inv = 1.f / s;
#pragma unroll
    for (int i = 0; i < 16; ++i)
        po[lane + i * 32] = __float2half_rn(v[i] * inv);
}

// ================== AV: single fp16, 2-stage (B trans) ======================
// grid (4 cq, 64): y<32 -> att0 @ v_l -> y_g ; y>=32 -> att1 @ v_g -> y_l
__global__ __launch_bounds__(256, 2)
void av_mma_kernel(const fp16* __restrict__ a1, const fp16* __restrict__ qk1,
                   fp16* __restrict__ y1) {
    extern __shared__ unsigned char dsm[];
    const uint32_t sb = smem_u32(dsm);
    const size_t QKV_N = (size_t)NB * CCH * HW;
    const size_t ATT_N = (size_t)NB * NHD * 512 * 512;

    int tid = threadIdx.x, wid = tid >> 5, lid = tid & 31;
    int warp_m = wid >> 2, warp_n = wid & 3;
    int z = blockIdx.y, sel = z >> 5, nh = z & 31;
    int n = nh >> 3, h = nh & 7;
    int cq0 = blockIdx.x * 128;
    const fp16* ab = a1 + sel * ATT_N + (size_t)(n * NHD + h) * 512 * 512;
    size_t vbo = (size_t)n * (CCH * HW) + h * DHEAD;
    const fp16* vb = qk1 + (sel ? 5 : 2) * QKV_N + vbo;

    float acc[4][4][4];
#pragma unroll
    for (int mt = 0; mt < 4; ++mt)
#pragma unroll
        for (int nt = 0; nt < 4; ++nt)
#pragma unroll
            for (int kk = 0; kk < 4; ++kk) acc[mt][nt][kk] = 0.f;

    int grp = lid >> 3, lr = lid & 7;
    uint32_t a_base = (uint32_t)((warp_m * 64 + (grp & 1) * 8 + lr) * ROWB + (grp >> 1) * 16);
    int l16 = lid & 15;
    uint32_t bt_base = (uint32_t)(l16 * ROW2 + warp_n * 64);

    int row = tid >> 1, half = tid & 1;
    uint32_t dstA = (uint32_t)(row * ROWB + half * 32);
    int ckr = tid >> 3, seg = tid & 7;
    uint32_t dstB = (uint32_t)(ckr * ROW2 + seg * 32);

    auto prefetch = [&](int ch, int st) {
        uint32_t s0b = sb + st * STGN;
        int ci0 = ch << 5;
        size_t aof = (size_t)(cq0 + row) * 512 + ci0 + half * 16;
        uint32_t da = s0b + dstA;
        CPA(da,      ab + aof,     16u);
        CPA(da + 16, ab + aof + 8, 16u);
        size_t vof = (size_t)(ci0 + ckr) * HW + seg * 16;
        uint32_t db = s0b + MATB + dstB;
        CPA(db,      vb + vof,     16u);
        CPA(db + 16, vb + vof + 8, 16u);
    };

    prefetch(0, 0); CP_COMMIT();
    for (int ch = 0; ch < 16; ++ch) {
        if (ch + 1 < 16) { prefetch(ch + 1, (ch + 1) & 1); CP_COMMIT(); CP_WAIT1(); }
        else CP_WAIT0();
        __syncthreads();
        mma_phase_nt(sb + (ch & 1) * STGN, a_base, bt_base, acc);
        __syncthreads();
    }

    fp16* yb = y1 + (sel ? QKV_N : 0) + vbo;
#pragma unroll
    for (int mt = 0; mt < 4; ++mt) {
        int m = cq0 + warp_m * 64 + mt * 16 + (lid >> 2);
#pragma unroll
        for (int nt = 0; nt < 4; ++nt) {
            int dc = warp_n * 32 + nt * 8 + (lid & 3) * 2;
            __half2 p0 = __floats2half2_rn(acc[mt][nt][0], acc[mt][nt][1]);
            __half2 p1 = __floats2half2_rn(acc[mt][nt][2], acc[mt][nt][3]);
            *(uint32_t*)&yb[(size_t)m * HW + dc] = *(uint32_t*)&p0;
            *(uint32_t*)&yb[(size_t)(m + 8) * HW + dc] = *(uint32_t*)&p1;
        }
    }
}

// ========= 1x1 proj + residual: single fp16, 2-stage (B trans) ==============
// grid (8 s, 4 co, 8): z<4 -> Wp1 @ y_l + x_l -> out_l ; else Wp2 @ y_g + x_g
__global__ __launch_bounds__(256, 2)
void proj_mma_kernel(const fp16* __restrict__ y1, const fp16* __restrict__ wp1,
                     const float* __restrict__ x_l, const float* __restrict__ x_g,
                     const float* __restrict__ rwp, float* __restrict__ out) {
    extern __shared__ unsigned char dsm[];
    const uint32_t sb = smem_u32(dsm);
    const size_t QKV_N = (size_t)NB * CCH * HW;

    int tid = threadIdx.x, wid = tid >> 5, lid = tid & 31;
    int warp_m = wid >> 2, warp_n = wid & 3;
    int z = blockIdx.z, sel = z >> 2, n = z & 3;    // sel 0: out_l, 1: out_g
    int sp0 = blockIdx.x * 128, co0 = blockIdx.y * 128;
    const fp16* yb = y1 + (sel ? 0 : QKV_N) + (size_t)n * (CCH * HW);
    const fp16* wb = wp1 + (size_t)sel * 512 * 512;
    const float* xres = sel ? x_g : x_l;
    float* outb = out + (size_t)sel * QKV_N;

    float acc[4][4][4];
#pragma unroll
    for (int mt = 0; mt < 4; ++mt)
#pragma unroll
        for (int nt = 0; nt < 4; ++nt)
#pragma unroll
            for (int kk = 0; kk < 4; ++kk) acc[mt][nt][kk] = 0.f;

    int grp = lid >> 3, lr = lid & 7;
    uint32_t a_base = (uint32_t)((warp_m * 64 + (grp & 1) * 8 + lr) * ROWB + (grp >> 1) * 16);
    int l16 = lid & 15;
    uint32_t bt_base = (uint32_t)(l16 * ROW2 + warp_n * 64);

    int row = tid >> 1, half = tid & 1;
    uint32_t dstA = (uint32_t)(row * ROWB + half * 32);
    int cir = tid >> 3, seg = tid & 7;
    uint32_t dstB = (uint32_t)(cir * ROW2 + seg * 32);

    auto prefetch = [&](int ch, int st) {
        uint32_t s0b = sb + st * STGN;
        int ci0 = ch << 5;
        size_t wof = (size_t)(co0 + row) * 512 + ci0 + half * 16;
        uint32_t da = s0b + dstA;
        CPA(da,      wb + wof,     16u);
        CPA(da + 16, wb + wof + 8, 16u);
        size_t yof = (size_t)(ci0 + cir) * HW + sp0 + seg * 16;
        uint32_t db = s0b + MATB + dstB;
        CPA(db,      yb + yof,     16u);
        CPA(db + 16, yb + yof + 8, 16u);
    };

    prefetch(0, 0); CP_COMMIT();
    for (int ch = 0; ch < 16; ++ch) {
        if (ch + 1 < 16) { prefetch(ch + 1, (ch + 1) & 1); CP_COMMIT(); CP_WAIT1(); }
        else CP_WAIT0();
        __syncthreads();
        mma_phase_nt(sb + (ch & 1) * STGN, a_base, bt_base, acc);
        __syncthreads();
    }

    float rw = *rwp;
#pragma unroll
    for (int mt = 0; mt < 4; ++mt) {
        int m = co0 + warp_m * 64 + mt * 16 + (lid >> 2);
#pragma unroll
        for (int nt = 0; nt < 4; ++nt) {
            int sc = sp0 + warp_n * 32 + nt * 8 + (lid & 3) * 2;
            size_t b0 = ((size_t)n * CCH + m) * HW + sc;
            size_t b1 = ((size_t)n * CCH + m + 8) * HW + sc;
            float2 x0 = *(const float2*)(xres + b0);
            float2 x1 = *(const float2*)(xres + b1);
            *(float2*)(outb + b0) = make_float2(x0.x + rw * acc[mt][nt][0],
                                                x0.y + rw * acc[mt][nt][1]);
            *(float2*)(outb + b1) = make_float2(x1.x + rw * acc[mt][nt][2],
                                                x1.y + rw * acc[mt][nt][3]);
        }
    }
}

// ------------------------------- launcher -----------------------------------
extern "C" void kernel_launch(void* const* d_in, const int* in_sizes, int n_in,
                              void* d_out, int out_size) {
    (void)in_sizes; (void)n_in; (void)out_size;
    const float* x_l = (const float*)d_in[0];
    const float* x_g = (const float*)d_in[1];
    const float* Wp1 = (const float*)d_in[8];
    const float* Wp2 = (const float*)d_in[9];
    const float* rw  = (const float*)d_in[10];
    float* out = (float*)d_out;

    void* p;
    cudaGetSymbolAddress(&p, g_w1);  fp16* w1  = (fp16*)p;
    cudaGetSymbolAddress(&p, g_x1);  fp16* x1  = (fp16*)p;
    cudaGetSymbolAddress(&p, g_q1);  fp16* q1  = (fp16*)p;
    cudaGetSymbolAddress(&p, g_att); float* attp = (float*)p;
    cudaGetSymbolAddress(&p, g_a1);  fp16* a1  = (fp16*)p;
    cudaGetSymbolAddress(&p, g_y1);  fp16* y1  = (fp16*)p;
    cudaGetSymbolAddress(&p, g_wp1); fp16* wp1 = (fp16*)p;

    cudaFuncSetAttribute(conv_mma_kernel, cudaFuncAttributeMaxDynamicSharedMemorySize, SM23);
    cudaFuncSetAttribute(qk_mma_kernel,   cudaFuncAttributeMaxDynamicSharedMemorySize, SM22);
    cudaFuncSetAttribute(av_mma_kernel,   cudaFuncAttributeMaxDynamicSharedMemorySize, SMN);
    cudaFuncSetAttribute(proj_mma_kernel, cudaFuncAttributeMaxDynamicSharedMemorySize, SMN);

    prep_w3<<<dim3(1024, 6), 256>>>(
        (const float*)d_in[2], (const float*)d_in[3], (const float*)d_in[4],
        (const float*)d_in[5], (const float*)d_in[6], (const float*)d_in[7], w1);
    prep_wp<<<dim3(1024, 2), 256>>>(Wp1, Wp2, wp1);
    transpose_x<<<dim3(32, 16, 8), dim3(32, 8)>>>(x_l, x_g, x1);

    // buffers: 0 kl, 1 ql, 2 vl, 3 kg, 4 qg, 5 vg
    conv_mma_kernel<<<dim3(8, 4, 24), 256, SM23>>>(x1, w1, q1);

    qk_mma_kernel<<<dim3(4, 4, 64), 256, SM22>>>(q1, attp);

    softmax_kernel<<<4096, 256>>>(attp, a1);

    av_mma_kernel<<<dim3(4, 64), 256, SMN>>>(a1, q1, y1);

    proj_mma_kernel<<<dim3(8, 4, 8), 256, SMN>>>(y1, wp1, x_l, x_g, rw, out);
}

// round 13
// speedup vs baseline: 1.4571x; 1.4571x over previous
#include <cuda_runtime.h>
#include <cuda_fp16.h>
#include <cstdint>

// ---------------------------------------------------------------------------
// CrossAttention on GB300 (sm_103a; plain compute_103 -> mma.sync fp16).
// R13: single fp16 x single fp16 in ALL GEMMs. Conv uses the PROVEN R11
// 2-stage / 2-barrier cp.async pipeline (R12's 3-stage/1-barrier regressed);
// qk/av/proj/softmax are the R12 single-precision kernels.
// ---------------------------------------------------------------------------

#define NB   4
#define CCH  512
#define HW   1024
#define NHD  8
#define DHEAD 128

typedef __half fp16;

// Scratch (no allocations -> __device__ globals)
__device__ fp16  g_w1[6][9 * 512 * 512];           // [conv][r][co][ci]
__device__ fp16  g_x1[2][NB * HW * CCH];           // [n][hw][ci]
__device__ fp16  g_q1[6][NB * CCH * HW];           // kl,ql,vl,kg,qg,vg
__device__ float g_att[2][NB * NHD * 512 * 512];   // pre-softmax
__device__ fp16  g_a1[2][NB * NHD * 512 * 512];    // post-softmax fp16
__device__ fp16  g_y1[2][NB * CCH * HW];           // y_g, y_l
__device__ fp16  g_wp1[2][512 * 512];

// ============================ helpers =======================================
__device__ __forceinline__ uint32_t smem_u32(const void* p) {
    uint32_t a;
    asm("{ .reg .u64 t; cvta.to.shared.u64 t, %1; cvt.u32.u64 %0, t; }"
        : "=r"(a) : "l"(p));
    return a;
}

__device__ __forceinline__ void mma_f16(float* c, const uint32_t* a, const uint32_t* b) {
    asm volatile(
        "mma.sync.aligned.m16n8k16.row.col.f32.f16.f16.f32 "
        "{%0,%1,%2,%3}, {%4,%5,%6,%7}, {%8,%9}, {%0,%1,%2,%3};"
        : "+f"(c[0]), "+f"(c[1]), "+f"(c[2]), "+f"(c[3])
        : "r"(a[0]), "r"(a[1]), "r"(a[2]), "r"(a[3]), "r"(b[0]), "r"(b[1]));
}

#define LDSM4(r0, r1, r2, r3, addr) \
    asm volatile("ldmatrix.sync.aligned.m8n8.x4.shared.b16 {%0,%1,%2,%3}, [%4];" \
                 : "=r"(r0), "=r"(r1), "=r"(r2), "=r"(r3) : "r"(addr))

#define LDSM2T(r0, r1, addr) \
    asm volatile("ldmatrix.sync.aligned.m8n8.x2.trans.shared.b16 {%0,%1}, [%2];" \
                 : "=r"(r0), "=r"(r1) : "r"(addr))

#define CPA(dst, src, sz) \
    asm volatile("cp.async.ca.shared.global [%0], [%1], 16, %2;" \
                 :: "r"(dst), "l"(src), "r"(sz) : "memory")
#define CP_COMMIT() asm volatile("cp.async.commit_group;" ::: "memory")
#define CP_WAIT1()  asm volatile("cp.async.wait_group 1;" ::: "memory")
#define CP_WAIT0()  asm volatile("cp.async.wait_group 0;" ::: "memory")

// ============================ prep kernels ==================================
// w [co][ci][3][3] -> [conv][r][co][ci] fp16
__global__ void prep_w3(const float* __restrict__ w0, const float* __restrict__ w1,
                        const float* __restrict__ w2, const float* __restrict__ w3,
                        const float* __restrict__ w4, const float* __restrict__ w5,
                        fp16* __restrict__ wo) {
    const float* ws[6] = {w0, w1, w2, w3, w4, w5};
    int conv = blockIdx.y;
    const float* w = ws[conv];
    int t = blockIdx.x * 256 + threadIdx.x;
    int co = t >> 9, ci = t & 511;
    float v[9];
#pragma unroll
    for (int r = 0; r < 9; ++r) v[r] = w[(size_t)t * 9 + r];
#pragma unroll
    for (int r = 0; r < 9; ++r)
        wo[(((size_t)conv * 9 + r) * 512 + co) * 512 + ci] = __float2half_rn(v[r]);
}
__global__ void prep_wp(const float* __restrict__ wp1, const float* __restrict__ wp2,
                        fp16* __restrict__ wo) {
    int pidx = blockIdx.y;
    const float* w = pidx ? wp2 : wp1;
    int idx = blockIdx.x * 256 + threadIdx.x;
    wo[(size_t)pidx * 512 * 512 + idx] = __float2half_rn(w[idx]);
}
// x [n][c][hw] -> xt [n][hw][c] fp16
__global__ void transpose_x(const float* __restrict__ xl, const float* __restrict__ xg,
                            fp16* __restrict__ xt1) {
    __shared__ float tile[32][33];
    int zt = blockIdx.z, tsel = zt >> 2, n = zt & 3;
    const float* x = (tsel ? xg : xl) + (size_t)n * (CCH * HW);
    size_t ob = (size_t)tsel * NB * HW * CCH + (size_t)n * (HW * CCH);
    int hw0 = blockIdx.x * 32, c0 = blockIdx.y * 32;
    int tx = threadIdx.x, ty = threadIdx.y;
#pragma unroll
    for (int i = 0; i < 32; i += 8)
        tile[ty + i][tx] = x[(size_t)(c0 + ty + i) * HW + hw0 + tx];
    __syncthreads();
#pragma unroll
    for (int i = 0; i < 32; i += 8)
        xt1[ob + (size_t)(hw0 + ty + i) * CCH + c0 + tx] =
            __float2half_rn(tile[tx][ty + i]);
}

// ============================ layout consts =================================
#define ROWB 80
#define MATB (128 * ROWB)             // 10240
#define ROW2 272
#define MATB2 (32 * ROW2)             // 8704
#define STG2 (2 * MATB)               // nn stage: A B          20480
#define SM22 (2 * STG2)               // 2-stage                40960
#define STGN (MATB + MATB2)           // nt stage: A B          18944
#define SMN  (2 * STGN)               // 37888

// ======================= mma inner phases (single A) ========================
__device__ __forceinline__ void mma_phase_nn(uint32_t st, uint32_t a_base,
                                             uint32_t b_base, float acc[4][4][4]) {
    uint32_t sA = st, sB = st + MATB;
#pragma unroll
    for (int kt = 0; kt < 2; ++kt) {
        uint32_t aa[4][4], bb[4][2];
#pragma unroll
        for (int mt = 0; mt < 4; ++mt) {
            uint32_t ad = a_base + (uint32_t)(mt * 16 * ROWB + kt * 32);
            LDSM4(aa[mt][0], aa[mt][1], aa[mt][2], aa[mt][3], sA + ad);
        }
#pragma unroll
        for (int p = 0; p < 2; ++p) {
            uint32_t bd = b_base + (uint32_t)(p * 16 * ROWB + kt * 32);
            uint32_t r0, r1, r2, r3;
            LDSM4(r0, r1, r2, r3, sB + bd);
            bb[2 * p][0] = r0; bb[2 * p][1] = r2;
            bb[2 * p + 1][0] = r1; bb[2 * p + 1][1] = r3;
        }
#pragma unroll
        for (int mt = 0; mt < 4; ++mt)
#pragma unroll
            for (int nt = 0; nt < 4; ++nt)
                mma_f16(acc[mt][nt], aa[mt], bb[nt]);
    }
}

__device__ __forceinline__ void mma_phase_nt(uint32_t st, uint32_t a_base,
                                             uint32_t bt_base, float acc[4][4][4]) {
    uint32_t sA = st, sB = st + MATB;
#pragma unroll
    for (int kt = 0; kt < 2; ++kt) {
        uint32_t aa[4][4], bb[4][2];
#pragma unroll
        for (int mt = 0; mt < 4; ++mt) {
            uint32_t ad = a_base + (uint32_t)(mt * 16 * ROWB + kt * 32);
            LDSM4(aa[mt][0], aa[mt][1], aa[mt][2], aa[mt][3], sA + ad);
        }
#pragma unroll
        for (int nt = 0; nt < 4; ++nt) {
            uint32_t bd = bt_base + (uint32_t)(kt * 16 * ROW2 + nt * 16);
            LDSM2T(bb[nt][0], bb[nt][1], sB + bd);
        }
#pragma unroll
        for (int mt = 0; mt < 4; ++mt)
#pragma unroll
            for (int nt = 0; nt < 4; ++nt)
                mma_f16(acc[mt][nt], aa[mt], bb[nt]);
    }
}

// ===== conv 3x3: single fp16, R11-proven 2-stage / 2-barrier pipeline =======
// grid (8 s-tiles, 4 co-tiles, 24 conv*n)
__global__ __launch_bounds__(256, 2)
void conv_mma_kernel(const fp16* __restrict__ xt1, const fp16* __restrict__ w1,
                     fp16* __restrict__ q1) {
    extern __shared__ unsigned char dsm[];
    const uint32_t sb = smem_u32(dsm);

    int tid = threadIdx.x, wid = tid >> 5, lid = tid & 31;
    int warp_m = wid >> 2, warp_n = wid & 3;
    int sp0 = blockIdx.x * 128, co0 = blockIdx.y * 128;
    int conv = blockIdx.z >> 2, n = blockIdx.z & 3;
    const fp16* xb = xt1 + ((size_t)(conv < 3 ? 0 : 1) * NB + n) * (HW * CCH);
    const fp16* wb = w1 + (size_t)conv * (9 * 512 * 512);
    fp16* o1 = q1 + ((size_t)conv * NB + n) * (CCH * HW);

    float acc[4][4][4];
#pragma unroll
    for (int mt = 0; mt < 4; ++mt)
#pragma unroll
        for (int nt = 0; nt < 4; ++nt)
#pragma unroll
            for (int k = 0; k < 4; ++k) acc[mt][nt][k] = 0.f;

    int grp = lid >> 3, lr = lid & 7;
    uint32_t a_base = (uint32_t)((warp_m * 64 + (grp & 1) * 8 + lr) * ROWB + (grp >> 1) * 16);
    uint32_t b_base = (uint32_t)((warp_n * 32 + (grp & 1) * 8 + lr) * ROWB + (grp >> 1) * 16);

    int row = tid >> 1, half = tid & 1;
    uint32_t dstA = (uint32_t)(row * ROWB + half * 32);

    auto prefetch = [&](int ch, int st) {
        uint32_t s0b = sb + st * STG2;
        int r = ch >> 4, ci0 = (ch & 15) << 5;
        int dy = r / 3 - 1, dx = r % 3 - 1;
        size_t wof = ((size_t)r * 512 + co0 + row) * 512 + ci0 + half * 16;
        uint32_t da = s0b + dstA;
        CPA(da,      wb + wof,     16u);
        CPA(da + 16, wb + wof + 8, 16u);
        int s = sp0 + row;
        int yy = (s >> 5) + dy, xx = (s & 31) + dx;
        bool ok = ((unsigned)yy < 32u) && ((unsigned)xx < 32u);
        size_t xof = ok ? ((size_t)(yy * 32 + xx) * 512 + ci0 + half * 16) : 0;
        uint32_t sz = ok ? 16u : 0u;
        uint32_t db = s0b + MATB + dstA;
        CPA(db,      xb + xof,     sz);
        CPA(db + 16, xb + xof + 8, sz);
    };

    // R11-proven: prefetch at top, wait, barrier, mma, barrier.
    prefetch(0, 0); CP_COMMIT();
    for (int ch = 0; ch < 144; ++ch) {
        if (ch + 1 < 144) { prefetch(ch + 1, (ch + 1) & 1); CP_COMMIT(); CP_WAIT1(); }
        else CP_WAIT0();
        __syncthreads();
        mma_phase_nn(sb + (ch & 1) * STG2, a_base, b_base, acc);
        __syncthreads();
    }

#pragma unroll
    for (int mt = 0; mt < 4; ++mt) {
        int m = co0 + warp_m * 64 + mt * 16 + (lid >> 2);
#pragma unroll
        for (int nt = 0; nt < 4; ++nt) {
            int sc = sp0 + warp_n * 32 + nt * 8 + (lid & 3) * 2;
            __half2 p0 = __floats2half2_rn(acc[mt][nt][0], acc[mt][nt][1]);
            __half2 p1 = __floats2half2_rn(acc[mt][nt][2], acc[mt][nt][3]);
            *(uint32_t*)&o1[(size_t)m * HW + sc] = *(uint32_t*)&p0;
            *(uint32_t*)&o1[(size_t)(m + 8) * HW + sc] = *(uint32_t*)&p1;
        }
    }
}

// ================== QK^T: single fp16, 2-stage cp.async =====================
// grid (4 ck, 4 cq, 64): z<32 -> (q_g,k_l)->att0 ; z>=32 -> (q_l,k_g)->att1
__global__ __launch_bounds__(256, 2)
void qk_mma_kernel(const fp16* __restrict__ qk1, float* __restrict__ att) {
    extern __shared__ unsigned char dsm[];
    const uint32_t sb = smem_u32(dsm);
    const size_t QKV_N = (size_t)NB * CCH * HW;
    const size_t ATT_N = (size_t)NB * NHD * 512 * 512;

    int tid = threadIdx.x, wid = tid >> 5, lid = tid & 31;
    int warp_m = wid >> 2, warp_n = wid & 3;
    int z = blockIdx.z, sel = z >> 5, nh = z & 31;
    int n = nh >> 3, h = nh & 7;
    int ck0 = blockIdx.x * 128, cq0 = blockIdx.y * 128;
    size_t base = (size_t)n * (CCH * HW) + h * DHEAD;
    const fp16* qb = qk1 + (sel ? 1 : 4) * QKV_N + base;
    const fp16* kb = qk1 + (sel ? 3 : 0) * QKV_N + base;

    float acc[4][4][4];
#pragma unroll
    for (int mt = 0; mt < 4; ++mt)
#pragma unroll
        for (int nt = 0; nt < 4; ++nt)
#pragma unroll
            for (int kk = 0; kk < 4; ++kk) acc[mt][nt][kk] = 0.f;

    int grp = lid >> 3, lr = lid & 7;
    uint32_t a_base = (uint32_t)((warp_m * 64 + (grp & 1) * 8 + lr) * ROWB + (grp >> 1) * 16);
    uint32_t b_base = (uint32_t)((warp_n * 32 + (grp & 1) * 8 + lr) * ROWB + (grp >> 1) * 16);

    int row = tid >> 1, half = tid & 1;
    uint32_t dstA = (uint32_t)(row * ROWB + half * 32);

    auto prefetch = [&](int ch, int st) {
        uint32_t s0b = sb + st * STG2;
        int ci0 = ch << 5;
        size_t qof = (size_t)(cq0 + row) * HW + ci0 + half * 16;
        size_t kof = (size_t)(ck0 + row) * HW + ci0 + half * 16;
        uint32_t da = s0b + dstA;
        CPA(da,      qb + qof,     16u);
        CPA(da + 16, qb + qof + 8, 16u);
        uint32_t db = s0b + MATB + dstA;
        CPA(db,      kb + kof,     16u);
        CPA(db + 16, kb + kof + 8, 16u);
    };

    prefetch(0, 0); CP_COMMIT();
    for (int ch = 0; ch < 4; ++ch) {
        if (ch + 1 < 4) { prefetch(ch + 1, (ch + 1) & 1); CP_COMMIT(); CP_WAIT1(); }
        else CP_WAIT0();
        __syncthreads();
        mma_phase_nn(sb + (ch & 1) * STG2, a_base, b_base, acc);
        __syncthreads();
    }

    const float SC = 0.08838834764831845f;   // 1/sqrt(128)
    float* ab = att + sel * ATT_N + (size_t)(n * NHD + h) * 512 * 512;
#pragma unroll
    for (int mt = 0; mt < 4; ++mt) {
        int m = cq0 + warp_m * 64 + mt * 16 + (lid >> 2);
#pragma unroll
        for (int nt = 0; nt < 4; ++nt) {
            int sc = ck0 + warp_n * 32 + nt * 8 + (lid & 3) * 2;
            *(float2*)(ab + (size_t)m * 512 + sc) =
                make_float2(acc[mt][nt][0] * SC, acc[mt][nt][1] * SC);
            *(float2*)(ab + (size_t)(m + 8) * 512 + sc) =
                make_float2(acc[mt][nt][2] * SC, acc[mt][nt][3] * SC);
        }
    }
}

// ----------------- softmax: fp32 in -> fp16 out ------------------------------
__global__ void softmax_kernel(const float* __restrict__ att, fp16* __restrict__ a1) {
    int row  = blockIdx.x * 8 + (threadIdx.x >> 5);
    int lane = threadIdx.x & 31;
    const float* p = att + (size_t)row * 512;
    fp16* po = a1 + (size_t)row * 512;
    float v[16];
    float m = -1e30f;
#pragma unroll
    for (int i = 0; i < 16; ++i) { v[i] = p[lane + i * 32]; m = fmaxf(m, v[i]); }
#pragma unroll
    for (int o = 16; o; o >>= 1) m = fmaxf(m, __shfl_xor_sync(0xffffffffu, m, o));
    float s = 0.f;
#pragma unroll
    for (int i = 0; i < 16; ++i) { v[i] = __expf(v[i] - m); s += v[i]; }
#pragma unroll
    for (int o = 16; o; o >>= 1) s += __shfl_xor_sync(0xffffffffu, s, o);
    float inv = 1.f / s;
#pragma unroll
    for (int i = 0; i < 16; ++i)
        po[lane + i * 32] = __float2half_rn(v[i] * inv);
}

// ================== AV: single fp16, 2-stage (B trans) ======================
// grid (4 cq, 64): y<32 -> att0 @ v_l -> y_g ; y>=32 -> att1 @ v_g -> y_l
__global__ __launch_bounds__(256, 2)
void av_mma_kernel(const fp16* __restrict__ a1, const fp16* __restrict__ qk1,
                   fp16* __restrict__ y1) {
    extern __shared__ unsigned char dsm[];
    const uint32_t sb = smem_u32(dsm);
    const size_t QKV_N = (size_t)NB * CCH * HW;
    const size_t ATT_N = (size_t)NB * NHD * 512 * 512;

    int tid = threadIdx.x, wid = tid >> 5, lid = tid & 31;
    int warp_m = wid >> 2, warp_n = wid & 3;
    int z = blockIdx.y, sel = z >> 5, nh = z & 31;
    int n = nh >> 3, h = nh & 7;
    int cq0 = blockIdx.x * 128;
    const fp16* ab = a1 + sel * ATT_N + (size_t)(n * NHD + h) * 512 * 512;
    size_t vbo = (size_t)n * (CCH * HW) + h * DHEAD;
    const fp16* vb = qk1 + (sel ? 5 : 2) * QKV_N + vbo;

    float acc[4][4][4];
#pragma unroll
    for (int mt = 0; mt < 4; ++mt)
#pragma unroll
        for (int nt = 0; nt < 4; ++nt)
#pragma unroll
            for (int kk = 0; kk < 4; ++kk) acc[mt][nt][kk] = 0.f;

    int grp = lid >> 3, lr = lid & 7;
    uint32_t a_base = (uint32_t)((warp_m * 64 + (grp & 1) * 8 + lr) * ROWB + (grp >> 1) * 16);
    int l16 = lid & 15;
    uint32_t bt_base = (uint32_t)(l16 * ROW2 + warp_n * 64);

    int row = tid >> 1, half = tid & 1;
    uint32_t dstA = (uint32_t)(row * ROWB + half * 32);
    int ckr = tid >> 3, seg = tid & 7;
    uint32_t dstB = (uint32_t)(ckr * ROW2 + seg * 32);

    auto prefetch = [&](int ch, int st) {
        uint32_t s0b = sb + st * STGN;
        int ci0 = ch << 5;
        size_t aof = (size_t)(cq0 + row) * 512 + ci0 + half * 16;
        uint32_t da = s0b + dstA;
        CPA(da,      ab + aof,     16u);
        CPA(da + 16, ab + aof + 8, 16u);
        size_t vof = (size_t)(ci0 + ckr) * HW + seg * 16;
        uint32_t db = s0b + MATB + dstB;
        CPA(db,      vb + vof,     16u);
        CPA(db + 16, vb + vof + 8, 16u);
    };

    prefetch(0, 0); CP_COMMIT();
    for (int ch = 0; ch < 16; ++ch) {
        if (ch + 1 < 16) { prefetch(ch + 1, (ch + 1) & 1); CP_COMMIT(); CP_WAIT1(); }
        else CP_WAIT0();
        __syncthreads();
        mma_phase_nt(sb + (ch & 1) * STGN, a_base, bt_base, acc);
        __syncthreads();
    }

    fp16* yb = y1 + (sel ? QKV_N : 0) + vbo;
#pragma unroll
    for (int mt = 0; mt < 4; ++mt) {
        int m = cq0 + warp_m * 64 + mt * 16 + (lid >> 2);
#pragma unroll
        for (int nt = 0; nt < 4; ++nt) {
            int dc = warp_n * 32 + nt * 8 + (lid & 3) * 2;
            __half2 p0 = __floats2half2_rn(acc[mt][nt][0], acc[mt][nt][1]);
            __half2 p1 = __floats2half2_rn(acc[mt][nt][2], acc[mt][nt][3]);
            *(uint32_t*)&yb[(size_t)m * HW + dc] = *(uint32_t*)&p0;
            *(uint32_t*)&yb[(size_t)(m + 8) * HW + dc] = *(uint32_t*)&p1;
        }
    }
}

// ========= 1x1 proj + residual: single fp16, 2-stage (B trans) ==============
// grid (8 s, 4 co, 8): z<4 -> Wp1 @ y_l + x_l -> out_l ; else Wp2 @ y_g + x_g
__global__ __launch_bounds__(256, 2)
void proj_mma_kernel(const fp16* __restrict__ y1, const fp16* __restrict__ wp1,
                     const float* __restrict__ x_l, const float* __restrict__ x_g,
                     const float* __restrict__ rwp, float* __restrict__ out) {
    extern __shared__ unsigned char dsm[];
    const uint32_t sb = smem_u32(dsm);
    const size_t QKV_N = (size_t)NB * CCH * HW;

    int tid = threadIdx.x, wid = tid >> 5, lid = tid & 31;
    int warp_m = wid >> 2, warp_n = wid & 3;
    int z = blockIdx.z, sel = z >> 2, n = z & 3;    // sel 0: out_l, 1: out_g
    int sp0 = blockIdx.x * 128, co0 = blockIdx.y * 128;
    const fp16* yb = y1 + (sel ? 0 : QKV_N) + (size_t)n * (CCH * HW);
    const fp16* wb = wp1 + (size_t)sel * 512 * 512;
    const float* xres = sel ? x_g : x_l;
    float* outb = out + (size_t)sel * QKV_N;

    float acc[4][4][4];
#pragma unroll
    for (int mt = 0; mt < 4; ++mt)
#pragma unroll
        for (int nt = 0; nt < 4; ++nt)
#pragma unroll
            for (int kk = 0; kk < 4; ++kk) acc[mt][nt][kk] = 0.f;

    int grp = lid >> 3, lr = lid & 7;
    uint32_t a_base = (uint32_t)((warp_m * 64 + (grp & 1) * 8 + lr) * ROWB + (grp >> 1) * 16);
    int l16 = lid & 15;
    uint32_t bt_base = (uint32_t)(l16 * ROW2 + warp_n * 64);

    int row = tid >> 1, half = tid & 1;
    uint32_t dstA = (uint32_t)(row * ROWB + half * 32);
    int cir = tid >> 3, seg = tid & 7;
    uint32_t dstB = (uint32_t)(cir * ROW2 + seg * 32);

    auto prefetch = [&](int ch, int st) {
        uint32_t s0b = sb + st * STGN;
        int ci0 = ch << 5;
        size_t wof = (size_t)(co0 + row) * 512 + ci0 + half * 16;
        uint32_t da = s0b + dstA;
        CPA(da,      wb + wof,     16u);
        CPA(da + 16, wb + wof + 8, 16u);
        size_t yof = (size_t)(ci0 + cir) * HW + sp0 + seg * 16;
        uint32_t db = s0b + MATB + dstB;
        CPA(db,      yb + yof,     16u);
        CPA(db + 16, yb + yof + 8, 16u);
    };

    prefetch(0, 0); CP_COMMIT();
    for (int ch = 0; ch < 16; ++ch) {
        if (ch + 1 < 16) { prefetch(ch + 1, (ch + 1) & 1); CP_COMMIT(); CP_WAIT1(); }
        else CP_WAIT0();
        __syncthreads();
        mma_phase_nt(sb + (ch & 1) * STGN, a_base, bt_base, acc);
        __syncthreads();
    }

    float rw = *rwp;
#pragma unroll
    for (int mt = 0; mt < 4; ++mt) {
        int m = co0 + warp_m * 64 + mt * 16 + (lid >> 2);
#pragma unroll
        for (int nt = 0; nt < 4; ++nt) {
            int sc = sp0 + warp_n * 32 + nt * 8 + (lid & 3) * 2;
            size_t b0 = ((size_t)n * CCH + m) * HW + sc;
            size_t b1 = ((size_t)n * CCH + m + 8) * HW + sc;
            float2 x0 = *(const float2*)(xres + b0);
            float2 x1 = *(const float2*)(xres + b1);
            *(float2*)(outb + b0) = make_float2(x0.x + rw * acc[mt][nt][0],
                                                x0.y + rw * acc[mt][nt][1]);
            *(float2*)(outb + b1) = make_float2(x1.x + rw * acc[mt][nt][2],
                                                x1.y + rw * acc[mt][nt][3]);
        }
    }
}

// ------------------------------- launcher -----------------------------------
extern "C" void kernel_launch(void* const* d_in, const int* in_sizes, int n_in,
                              void* d_out, int out_size) {
    (void)in_sizes; (void)n_in; (void)out_size;
    const float* x_l = (const float*)d_in[0];
    const float* x_g = (const float*)d_in[1];
    const float* Wp1 = (const float*)d_in[8];
    const float* Wp2 = (const float*)d_in[9];
    const float* rw  = (const float*)d_in[10];
    float* out = (float*)d_out;

    void* p;
    cudaGetSymbolAddress(&p, g_w1);  fp16* w1  = (fp16*)p;
    cudaGetSymbolAddress(&p, g_x1);  fp16* x1  = (fp16*)p;
    cudaGetSymbolAddress(&p, g_q1);  fp16* q1  = (fp16*)p;
    cudaGetSymbolAddress(&p, g_att); float* attp = (float*)p;
    cudaGetSymbolAddress(&p, g_a1);  fp16* a1  = (fp16*)p;
    cudaGetSymbolAddress(&p, g_y1);  fp16* y1  = (fp16*)p;
    cudaGetSymbolAddress(&p, g_wp1); fp16* wp1 = (fp16*)p;

    cudaFuncSetAttribute(conv_mma_kernel, cudaFuncAttributeMaxDynamicSharedMemorySize, SM22);
    cudaFuncSetAttribute(qk_mma_kernel,   cudaFuncAttributeMaxDynamicSharedMemorySize, SM22);
    cudaFuncSetAttribute(av_mma_kernel,   cudaFuncAttributeMaxDynamicSharedMemorySize, SMN);
    cudaFuncSetAttribute(proj_mma_kernel, cudaFuncAttributeMaxDynamicSharedMemorySize, SMN);

    prep_w3<<<dim3(1024, 6), 256>>>(
        (const float*)d_in[2], (const float*)d_in[3], (const float*)d_in[4],
        (const float*)d_in[5], (const float*)d_in[6], (const float*)d_in[7], w1);
    prep_wp<<<dim3(1024, 2), 256>>>(Wp1, Wp2, wp1);
    transpose_x<<<dim3(32, 16, 8), dim3(32, 8)>>>(x_l, x_g, x1);

    // buffers: 0 kl, 1 ql, 2 vl, 3 kg, 4 qg, 5 vg
    conv_mma_kernel<<<dim3(8, 4, 24), 256, SM22>>>(x1, w1, q1);

    qk_mma_kernel<<<dim3(4, 4, 64), 256, SM22>>>(q1, attp);

    softmax_kernel<<<4096, 256>>>(attp, a1);

    av_mma_kernel<<<dim3(4, 64), 256, SMN>>>(a1, q1, y1);

    proj_mma_kernel<<<dim3(8, 4, 8), 256, SMN>>>(y1, wp1, x_l, x_g, rw, out);
}